// round 4
// baseline (speedup 1.0000x reference)
#include <cuda_runtime.h>
#include <cstdint>

#define USER_NUM 50000
#define ITEM_NUM 50000
#define NTOT     100000
#define VT_DIM   512
#define CAT_DIM  32
#define HID      128
#define OUTD     64

// ---------------- static scratch (no allocs allowed) ----------------
__device__ float g_x0[(size_t)NTOT * HID];    // [user; item_feat]
__device__ float g_h1[(size_t)NTOT * HID];    // x0 @ w1_l.T
__device__ float g_s1[(size_t)NTOT * HID];    // edge-aggregated sums (conv1)
__device__ float g_x1[(size_t)NTOT * HID];    // leaky(conv1)
__device__ float g_h2[(size_t)NTOT * OUTD];   // x1 @ w2_l.T
__device__ float g_s2[(size_t)NTOT * OUTD];   // edge-aggregated sums (conv2)
__device__ float g_cat[(size_t)ITEM_NUM * CAT_DIM];
__device__ float g_deg[NTOT];

// ---------------- helpers ----------------
__device__ __forceinline__ void red_add_v4(float* p, float4 v) {
    asm volatile("red.global.add.v4.f32 [%0], {%1, %2, %3, %4};"
                 :: "l"(p), "f"(v.x), "f"(v.y), "f"(v.z), "f"(v.w) : "memory");
}

// packed dual-fp32 FMA: d = a*b + d  (SASS FFMA2)
__device__ __forceinline__ void ffma2(unsigned long long& d,
                                      unsigned long long a,
                                      unsigned long long b) {
    asm("fma.rn.f32x2 %0, %1, %2, %0;" : "+l"(d) : "l"(a), "l"(b));
}
__device__ __forceinline__ void unpack2(unsigned long long v, float& lo, float& hi) {
    asm("mov.b64 {%0, %1}, %2;" : "=f"(lo), "=f"(hi) : "l"(v));
}

// ---------------- zero scratch ----------------
__global__ void zero_fill_kernel() {
    size_t n1 = (size_t)NTOT * HID / 4;
    size_t n2 = (size_t)NTOT * OUTD / 4;
    size_t stride = (size_t)gridDim.x * blockDim.x;
    size_t gid = (size_t)blockIdx.x * blockDim.x + threadIdx.x;
    float4 z = make_float4(0.f, 0.f, 0.f, 0.f);
    for (size_t i = gid; i < n1; i += stride) ((float4*)g_s1)[i] = z;
    for (size_t i = gid; i < n2; i += stride) ((float4*)g_s2)[i] = z;
    for (size_t i = gid; i < NTOT; i += stride) g_deg[i] = 0.f;
}

// ---------------- copy user rows into x0 ----------------
__global__ void copy_user_kernel(const float* __restrict__ user) {
    size_t n = (size_t)USER_NUM * HID / 4;
    size_t gid = (size_t)blockIdx.x * blockDim.x + threadIdx.x;
    if (gid < n) ((float4*)g_x0)[gid] = ((const float4*)user)[gid];
}

// ---------------- embedding bag (mean of ~5 rows of 32) ----------------
__global__ void catbag_kernel(const float* __restrict__ table,
                              const int* __restrict__ idx,
                              const int* __restrict__ offs,
                              int tot_idx) {
    int gid = blockIdx.x * blockDim.x + threadIdx.x;
    if (gid >= ITEM_NUM * 8) return;
    int bag  = gid >> 3;
    int comp = (gid & 7) * 4;
    int beg = offs[bag];
    int end = (bag + 1 < ITEM_NUM) ? offs[bag + 1] : tot_idx;
    float4 s = make_float4(0.f, 0.f, 0.f, 0.f);
    for (int j = beg; j < end; j++) {
        int ix = __ldg(&idx[j]);
        float4 t = *(const float4*)(table + (size_t)ix * CAT_DIM + comp);
        s.x += t.x; s.y += t.y; s.z += t.z; s.w += t.w;
    }
    float inv = 1.0f / (float)max(end - beg, 1);
    s.x *= inv; s.y *= inv; s.z *= inv; s.w *= inv;
    *(float4*)(g_cat + (size_t)bag * CAT_DIM + comp) = s;
}

// ---------------- degree ----------------
__global__ void deg_kernel(const int* __restrict__ dst, int E) {
    int stride = gridDim.x * blockDim.x;
    for (int e = blockIdx.x * blockDim.x + threadIdx.x; e < E; e += stride)
        atomicAdd(&g_deg[__ldg(&dst[e])], 1.0f);
}

// ---------------- edge scatter: s[dst] += h[src] ----------------
template <int NC>
__global__ void scatter_kernel(const float* __restrict__ h,
                               const int* __restrict__ src,
                               const int* __restrict__ dst,
                               float* __restrict__ s, int E) {
    constexpr int LPE = NC / 4;
    int lane = threadIdx.x & (LPE - 1);
    int eg = (blockIdx.x * blockDim.x + threadIdx.x) / LPE;
    int estride = (gridDim.x * blockDim.x) / LPE;
    for (int e = eg; e < E; e += estride) {
        int si = __ldg(&src[e]);
        int di = __ldg(&dst[e]);
        float4 v = *(const float4*)(h + (size_t)si * NC + lane * 4);
        red_add_v4(s + (size_t)di * NC + lane * 4, v);
    }
}

// ---- pipelined FFMA2 GEMM, duplicated-A smem tile ---------------------------
// C[M,NC] = A[M,K] @ W[NC,K]^T (+epilogue)
// BM=128, BK=16, 256 threads; thread tile 8 rows x NC/16 cols (split-N groups)
// EPI: 0 = plain, 1 = leaky(C + b + s/deg), 2 = C + b + s/deg
template <int NC, int EPI, bool FUSED>
__global__ __launch_bounds__(256, 2)
void gemm_kernel(const float* __restrict__ A, int K,
                 const float* __restrict__ A2,
                 const float* __restrict__ W,
                 const float* __restrict__ bias,
                 const float* __restrict__ sagg,
                 const float* __restrict__ degp,
                 float* __restrict__ C, int M) {
    constexpr int BM = 128, BK = 16;
    constexpr int WPT = NC / 64;      // W float4 loads/thread (2 or 1)
    constexpr int NG  = NC / 64;      // column groups (2 or 1)
    constexpr int CP2 = NC / 32;      // packed col-pairs per thread (4 or 2)
    constexpr int WST = NC + 4;       // Ws row stride
    constexpr int AST = 2 * BK + 8;   // AsD row stride (40 floats, 16B aligned)

    __shared__ float AsD[2][BM][AST]; // value-duplicated A tile
    __shared__ float Ws[2][BK][WST];

    int tid = threadIdx.x;
    int tx = tid & 15, ty = tid >> 4;
    int row0 = blockIdx.x * BM;
    int r0 = ty * 8;
    int c0 = tx * 4;

    unsigned long long acc2[8][CP2];
#pragma unroll
    for (int i = 0; i < 8; i++)
#pragma unroll
        for (int j = 0; j < CP2; j++) acc2[i][j] = 0ull;

    float4 ar[2], wr[WPT];
    int nch = K / BK;

    auto ldgA = [&](int ch) {
        int kk = ch * BK;
#pragma unroll
        for (int h = 0; h < 2; h++) {
            int f = tid + h * 256;
            int row = f >> 2;
            int kc = (f & 3) * 4;
            int grow = row0 + row;
            float4 v = make_float4(0.f, 0.f, 0.f, 0.f);
            if (grow < M) {
                if (!FUSED)
                    v = *(const float4*)(A + (size_t)grow * K + kk + kc);
                else if (kk < VT_DIM)
                    v = *(const float4*)(A + (size_t)grow * VT_DIM + kk + kc);
                else
                    v = *(const float4*)(A2 + (size_t)grow * CAT_DIM + (kk - VT_DIM) + kc);
            }
            ar[h] = v;
        }
    };
    auto ldgW = [&](int ch) {
        int kk = ch * BK;
#pragma unroll
        for (int h = 0; h < WPT; h++) {
            int f = tid + h * 256;
            int c = f >> 2;
            int kq = (f & 3) * 4;
            wr[h] = *(const float4*)(W + (size_t)c * K + kk + kq);
        }
    };
    auto sts = [&](int b) {
#pragma unroll
        for (int h = 0; h < 2; h++) {
            int f = tid + h * 256;
            int row = f >> 2;
            int kc = (f & 3) * 4;
            float4 v = ar[h];
            *(float4*)&AsD[b][row][2 * kc + 0] = make_float4(v.x, v.x, v.y, v.y);
            *(float4*)&AsD[b][row][2 * kc + 4] = make_float4(v.z, v.z, v.w, v.w);
        }
#pragma unroll
        for (int h = 0; h < WPT; h++) {
            int f = tid + h * 256;
            int c = f >> 2;
            int kq = (f & 3) * 4;
            Ws[b][kq + 0][c] = wr[h].x;
            Ws[b][kq + 1][c] = wr[h].y;
            Ws[b][kq + 2][c] = wr[h].z;
            Ws[b][kq + 3][c] = wr[h].w;
        }
    };
    auto compute = [&](int b) {
#pragma unroll
        for (int k2 = 0; k2 < BK; k2 += 2) {
            ulonglong2 w0[NG], w1[NG];
#pragma unroll
            for (int g = 0; g < NG; g++) {
                w0[g] = *(const ulonglong2*)&Ws[b][k2 + 0][c0 + g * 64];
                w1[g] = *(const ulonglong2*)&Ws[b][k2 + 1][c0 + g * 64];
            }
#pragma unroll
            for (int i = 0; i < 8; i++) {
                // one LDS.128: (a_k2, a_k2, a_k2+1, a_k2+1) packed pairs
                ulonglong2 aa = *(const ulonglong2*)&AsD[b][r0 + i][2 * k2];
#pragma unroll
                for (int g = 0; g < NG; g++) {
                    ffma2(acc2[i][2 * g + 0], aa.x, w0[g].x);
                    ffma2(acc2[i][2 * g + 1], aa.x, w0[g].y);
                    ffma2(acc2[i][2 * g + 0], aa.y, w1[g].x);
                    ffma2(acc2[i][2 * g + 1], aa.y, w1[g].y);
                }
            }
        }
    };

    // prologue
    ldgA(0); ldgW(0);
    sts(0);
    __syncthreads();

    for (int ch = 0; ch < nch; ch++) {
        int nb = ch & 1;
        if (ch + 1 < nch) { ldgA(ch + 1); ldgW(ch + 1); }
        compute(nb);
        if (ch + 1 < nch) sts(1 - nb);
        __syncthreads();
    }

    // epilogue
#pragma unroll
    for (int i = 0; i < 8; i++) {
        int gr = row0 + r0 + i;
        if (gr >= M) continue;
        float dinv = 0.f;
        if (EPI != 0) dinv = 1.0f / fmaxf(degp[gr], 1.0f);
#pragma unroll
        for (int g = 0; g < NG; g++) {
            int gc = c0 + g * 64;
            float4 v;
            unpack2(acc2[i][2 * g + 0], v.x, v.y);
            unpack2(acc2[i][2 * g + 1], v.z, v.w);
            if (EPI != 0) {
                float4 sv = *(const float4*)(sagg + (size_t)gr * NC + gc);
                v.x += bias[gc + 0] + sv.x * dinv;
                v.y += bias[gc + 1] + sv.y * dinv;
                v.z += bias[gc + 2] + sv.z * dinv;
                v.w += bias[gc + 3] + sv.w * dinv;
                if (EPI == 1) {
                    v.x = v.x > 0.f ? v.x : 0.01f * v.x;
                    v.y = v.y > 0.f ? v.y : 0.01f * v.y;
                    v.z = v.z > 0.f ? v.z : 0.01f * v.z;
                    v.w = v.w > 0.f ? v.w : 0.01f * v.w;
                }
            }
            *(float4*)(C + (size_t)gr * NC + gc) = v;
        }
    }
}

// ---------------- launch ----------------
extern "C" void kernel_launch(void* const* d_in, const int* in_sizes, int n_in,
                              void* d_out, int out_size) {
    const float* vt      = (const float*)d_in[0];
    const int*   cat_idx = (const int*)d_in[1];
    const int*   cat_off = (const int*)d_in[2];
    const int*   edge    = (const int*)d_in[3];
    const float* cat_tab = (const float*)d_in[4];
    const float* fuse_w  = (const float*)d_in[5];
    const float* user    = (const float*)d_in[6];
    const float* w1_l    = (const float*)d_in[7];
    const float* b1      = (const float*)d_in[8];
    const float* w1_r    = (const float*)d_in[9];
    const float* w2_l    = (const float*)d_in[10];
    const float* b2      = (const float*)d_in[11];
    const float* w2_r    = (const float*)d_in[12];

    int E = in_sizes[3] / 2;
    const int* src = edge;
    const int* dst = edge + E;
    int tot_idx = in_sizes[1];

    float *x0p, *h1p, *s1p, *x1p, *h2p, *s2p, *catp, *degp;
    cudaGetSymbolAddress((void**)&x0p, g_x0);
    cudaGetSymbolAddress((void**)&h1p, g_h1);
    cudaGetSymbolAddress((void**)&s1p, g_s1);
    cudaGetSymbolAddress((void**)&x1p, g_x1);
    cudaGetSymbolAddress((void**)&h2p, g_h2);
    cudaGetSymbolAddress((void**)&s2p, g_s2);
    cudaGetSymbolAddress((void**)&catp, g_cat);
    cudaGetSymbolAddress((void**)&degp, g_deg);

    const int grid_item = (ITEM_NUM + 127) / 128;   // 391
    const int grid_all  = (NTOT + 127) / 128;       // 782

    // 1. zero scratch
    zero_fill_kernel<<<2048, 256>>>();
    // 2. x0[0:USER] = user
    copy_user_kernel<<<(USER_NUM * HID / 4 + 255) / 256, 256>>>(user);
    // 3. cat embedding bag
    catbag_kernel<<<(ITEM_NUM * 8 + 255) / 256, 256>>>(cat_tab, cat_idx, cat_off, tot_idx);
    // 4. item_feat = [vt | cat] @ fuse_w.T  -> x0[USER:]
    gemm_kernel<128, 0, true><<<grid_item, 256>>>(
        vt, VT_DIM + CAT_DIM, catp, fuse_w, nullptr, nullptr, nullptr,
        x0p + (size_t)USER_NUM * HID, ITEM_NUM);
    // 5. degree
    deg_kernel<<<2048, 256>>>(dst, E);
    // 6. h1 = x0 @ w1_l.T
    gemm_kernel<128, 0, false><<<grid_all, 256>>>(
        x0p, HID, nullptr, w1_l, nullptr, nullptr, nullptr, h1p, NTOT);
    // 7. s1[dst] += h1[src]
    scatter_kernel<128><<<2048, 256>>>(h1p, src, dst, s1p, E);
    // 8. x1 = leaky(s1/deg + b1 + x0 @ w1_r.T)
    gemm_kernel<128, 1, false><<<grid_all, 256>>>(
        x0p, HID, nullptr, w1_r, b1, s1p, degp, x1p, NTOT);
    // 9. h2 = x1 @ w2_l.T
    gemm_kernel<64, 0, false><<<grid_all, 256>>>(
        x1p, HID, nullptr, w2_l, nullptr, nullptr, nullptr, h2p, NTOT);
    // 10. s2[dst] += h2[src]
    scatter_kernel<64><<<2048, 256>>>(h2p, src, dst, s2p, E);
    // 11. out = s2/deg + b2 + x1 @ w2_r.T
    gemm_kernel<64, 2, false><<<grid_all, 256>>>(
        x1p, HID, nullptr, w2_r, b2, s2p, degp, (float*)d_out, NTOT);
}

// round 5
// speedup vs baseline: 1.1065x; 1.1065x over previous
#include <cuda_runtime.h>
#include <cstdint>

#define USER_NUM 50000
#define ITEM_NUM 50000
#define NTOT     100000
#define VT_DIM   512
#define CAT_DIM  32
#define HID      128
#define OUTD     64

// ---------------- static scratch (no allocs allowed) ----------------
__device__ float g_x0[(size_t)NTOT * HID];    // [user; item_feat]
__device__ float g_h1[(size_t)NTOT * HID];    // x0 @ w1_l.T
__device__ float g_s1[(size_t)NTOT * HID];    // edge-aggregated sums (conv1)
__device__ float g_x1[(size_t)NTOT * HID];    // leaky(conv1)
__device__ float g_h2[(size_t)NTOT * OUTD];   // x1 @ w2_l.T
__device__ float g_s2[(size_t)NTOT * OUTD];   // edge-aggregated sums (conv2)
__device__ float g_cat[(size_t)ITEM_NUM * CAT_DIM];
__device__ float g_deg[NTOT];

// ---------------- helpers ----------------
__device__ __forceinline__ void red_add_v4(float* p, float4 v) {
    asm volatile("red.global.add.v4.f32 [%0], {%1, %2, %3, %4};"
                 :: "l"(p), "f"(v.x), "f"(v.y), "f"(v.z), "f"(v.w) : "memory");
}

// packed dual-fp32 FMA: d = a*b + d  (SASS FFMA2)
__device__ __forceinline__ void ffma2(unsigned long long& d,
                                      unsigned long long a,
                                      unsigned long long b) {
    asm("fma.rn.f32x2 %0, %1, %2, %0;" : "+l"(d) : "l"(a), "l"(b));
}
__device__ __forceinline__ unsigned long long pack_dup(float a) {
    unsigned long long r;
    asm("mov.b64 %0, {%1, %1};" : "=l"(r) : "f"(a));
    return r;
}
__device__ __forceinline__ void unpack2(unsigned long long v, float& lo, float& hi) {
    asm("mov.b64 {%0, %1}, %2;" : "=f"(lo), "=f"(hi) : "l"(v));
}

// ---------------- init: zero s1/s2/deg + copy user rows into x0 -------------
__global__ void init_kernel(const float* __restrict__ user) {
    size_t n1 = (size_t)NTOT * HID / 4;
    size_t n2 = (size_t)NTOT * OUTD / 4;
    size_t nu = (size_t)USER_NUM * HID / 4;
    size_t stride = (size_t)gridDim.x * blockDim.x;
    size_t gid = (size_t)blockIdx.x * blockDim.x + threadIdx.x;
    float4 z = make_float4(0.f, 0.f, 0.f, 0.f);
    for (size_t i = gid; i < n1; i += stride) ((float4*)g_s1)[i] = z;
    for (size_t i = gid; i < n2; i += stride) ((float4*)g_s2)[i] = z;
    for (size_t i = gid; i < NTOT; i += stride) g_deg[i] = 0.f;
    for (size_t i = gid; i < nu; i += stride)
        ((float4*)g_x0)[i] = ((const float4*)user)[i];
}

// ---------------- embedding bag (mean of ~5 rows of 32) ----------------
__global__ void catbag_kernel(const float* __restrict__ table,
                              const int* __restrict__ idx,
                              const int* __restrict__ offs,
                              int tot_idx) {
    int gid = blockIdx.x * blockDim.x + threadIdx.x;
    if (gid >= ITEM_NUM * 8) return;
    int bag  = gid >> 3;
    int comp = (gid & 7) * 4;
    int beg = offs[bag];
    int end = (bag + 1 < ITEM_NUM) ? offs[bag + 1] : tot_idx;
    float4 s = make_float4(0.f, 0.f, 0.f, 0.f);
    for (int j = beg; j < end; j++) {
        int ix = __ldg(&idx[j]);
        float4 t = *(const float4*)(table + (size_t)ix * CAT_DIM + comp);
        s.x += t.x; s.y += t.y; s.z += t.z; s.w += t.w;
    }
    float inv = 1.0f / (float)max(end - beg, 1);
    s.x *= inv; s.y *= inv; s.z *= inv; s.w *= inv;
    *(float4*)(g_cat + (size_t)bag * CAT_DIM + comp) = s;
}

// ---------------- degree ----------------
__global__ void deg_kernel(const int* __restrict__ dst, int E) {
    int stride = gridDim.x * blockDim.x;
    for (int e = blockIdx.x * blockDim.x + threadIdx.x; e < E; e += stride)
        atomicAdd(&g_deg[__ldg(&dst[e])], 1.0f);
}

// ---------------- edge scatter: s[dst] += h[src], 2-way unrolled ------------
template <int NC>
__global__ void scatter_kernel(const float* __restrict__ h,
                               const int* __restrict__ src,
                               const int* __restrict__ dst,
                               float* __restrict__ s, int E) {
    constexpr int LPE = NC / 4;
    int lane = threadIdx.x & (LPE - 1);
    int co = lane * 4;
    int eg = (blockIdx.x * blockDim.x + threadIdx.x) / LPE;
    int estride = (gridDim.x * blockDim.x) / LPE;
    for (int e = eg; e < E; e += 2 * estride) {
        int e2 = e + estride;
        int si1 = __ldg(&src[e]);
        int di1 = __ldg(&dst[e]);
        if (e2 < E) {
            int si2 = __ldg(&src[e2]);
            int di2 = __ldg(&dst[e2]);
            float4 v1 = *(const float4*)(h + (size_t)si1 * NC + co);
            float4 v2 = *(const float4*)(h + (size_t)si2 * NC + co);
            red_add_v4(s + (size_t)di1 * NC + co, v1);
            red_add_v4(s + (size_t)di2 * NC + co, v2);
        } else {
            float4 v1 = *(const float4*)(h + (size_t)si1 * NC + co);
            red_add_v4(s + (size_t)di1 * NC + co, v1);
        }
    }
}

// ---- pipelined FFMA2 GEMM: C[M,NC] = A[M,K] @ W[NC,K]^T (+epilogue) --------
// BM=128, BK=16, 256 threads; thread tile 8 rows x NC/16 cols (split-N groups)
// EPI: 0 = plain, 1 = leaky(C + b + s/deg), 2 = C + b + s/deg
template <int NC, int EPI, bool FUSED>
__global__ __launch_bounds__(256, 2)
void gemm_kernel(const float* __restrict__ A, int K,
                 const float* __restrict__ A2,
                 const float* __restrict__ W,
                 const float* __restrict__ bias,
                 const float* __restrict__ sagg,
                 const float* __restrict__ degp,
                 float* __restrict__ C, int M) {
    constexpr int BM = 128, BK = 16;
    constexpr int WPT = NC / 64;      // W float4 loads/thread (2 or 1)
    constexpr int NG  = NC / 64;      // column groups (2 or 1)
    constexpr int CP2 = NC / 32;      // packed col-pairs per thread (4 or 2)
    constexpr int WST = NC + 4;       // Ws row stride (conflict-free)

    __shared__ float As[2][BM][BK + 4];   // row stride 20 floats
    __shared__ float Ws[2][BK][WST];

    int tid = threadIdx.x;
    int tx = tid & 15, ty = tid >> 4;
    int row0 = blockIdx.x * BM;
    int r0 = ty * 8;
    int c0 = tx * 4;

    unsigned long long acc2[8][CP2];
#pragma unroll
    for (int i = 0; i < 8; i++)
#pragma unroll
        for (int j = 0; j < CP2; j++) acc2[i][j] = 0ull;

    float4 ar[2], wr[WPT];
    int nch = K / BK;

    auto ldgA = [&](int ch) {
        int kk = ch * BK;
#pragma unroll
        for (int h = 0; h < 2; h++) {
            int f = tid + h * 256;
            int row = f >> 2;
            int kc = (f & 3) * 4;
            int grow = row0 + row;
            float4 v = make_float4(0.f, 0.f, 0.f, 0.f);
            if (grow < M) {
                if (!FUSED)
                    v = *(const float4*)(A + (size_t)grow * K + kk + kc);
                else if (kk < VT_DIM)
                    v = *(const float4*)(A + (size_t)grow * VT_DIM + kk + kc);
                else
                    v = *(const float4*)(A2 + (size_t)grow * CAT_DIM + (kk - VT_DIM) + kc);
            }
            ar[h] = v;
        }
    };
    auto ldgW = [&](int ch) {
        int kk = ch * BK;
#pragma unroll
        for (int h = 0; h < WPT; h++) {
            int f = tid + h * 256;
            int c = f >> 2;
            int kq = (f & 3) * 4;
            wr[h] = *(const float4*)(W + (size_t)c * K + kk + kq);
        }
    };
    auto sts = [&](int b) {
#pragma unroll
        for (int h = 0; h < 2; h++) {
            int f = tid + h * 256;
            *(float4*)&As[b][f >> 2][(f & 3) * 4] = ar[h];
        }
#pragma unroll
        for (int h = 0; h < WPT; h++) {
            int f = tid + h * 256;
            int c = f >> 2;
            int kq = (f & 3) * 4;
            Ws[b][kq + 0][c] = wr[h].x;
            Ws[b][kq + 1][c] = wr[h].y;
            Ws[b][kq + 2][c] = wr[h].z;
            Ws[b][kq + 3][c] = wr[h].w;
        }
    };
    auto compute = [&](int b) {
#pragma unroll
        for (int k2 = 0; k2 < BK; k2 += 2) {
            ulonglong2 w0[NG], w1[NG];
#pragma unroll
            for (int g = 0; g < NG; g++) {
                w0[g] = *(const ulonglong2*)&Ws[b][k2 + 0][c0 + g * 64];
                w1[g] = *(const ulonglong2*)&Ws[b][k2 + 1][c0 + g * 64];
            }
#pragma unroll
            for (int i = 0; i < 8; i++) {
                float2 t = *(const float2*)&As[b][r0 + i][k2];
                unsigned long long pa0 = pack_dup(t.x);
                unsigned long long pa1 = pack_dup(t.y);
#pragma unroll
                for (int g = 0; g < NG; g++) {
                    ffma2(acc2[i][2 * g + 0], pa0, w0[g].x);
                    ffma2(acc2[i][2 * g + 1], pa0, w0[g].y);
                    ffma2(acc2[i][2 * g + 0], pa1, w1[g].x);
                    ffma2(acc2[i][2 * g + 1], pa1, w1[g].y);
                }
            }
        }
    };

    // prologue
    ldgA(0); ldgW(0);
    sts(0);
    __syncthreads();

    for (int ch = 0; ch < nch; ch++) {
        int nb = ch & 1;
        if (ch + 1 < nch) { ldgA(ch + 1); ldgW(ch + 1); }
        compute(nb);
        if (ch + 1 < nch) sts(1 - nb);
        __syncthreads();
    }

    // epilogue
#pragma unroll
    for (int i = 0; i < 8; i++) {
        int gr = row0 + r0 + i;
        if (gr >= M) continue;
        float dinv = 0.f;
        if (EPI != 0) dinv = 1.0f / fmaxf(degp[gr], 1.0f);
#pragma unroll
        for (int g = 0; g < NG; g++) {
            int gc = c0 + g * 64;
            float4 v;
            unpack2(acc2[i][2 * g + 0], v.x, v.y);
            unpack2(acc2[i][2 * g + 1], v.z, v.w);
            if (EPI != 0) {
                float4 sv = *(const float4*)(sagg + (size_t)gr * NC + gc);
                v.x += bias[gc + 0] + sv.x * dinv;
                v.y += bias[gc + 1] + sv.y * dinv;
                v.z += bias[gc + 2] + sv.z * dinv;
                v.w += bias[gc + 3] + sv.w * dinv;
                if (EPI == 1) {
                    v.x = v.x > 0.f ? v.x : 0.01f * v.x;
                    v.y = v.y > 0.f ? v.y : 0.01f * v.y;
                    v.z = v.z > 0.f ? v.z : 0.01f * v.z;
                    v.w = v.w > 0.f ? v.w : 0.01f * v.w;
                }
            }
            *(float4*)(C + (size_t)gr * NC + gc) = v;
        }
    }
}

// ---------------- launch ----------------
extern "C" void kernel_launch(void* const* d_in, const int* in_sizes, int n_in,
                              void* d_out, int out_size) {
    const float* vt      = (const float*)d_in[0];
    const int*   cat_idx = (const int*)d_in[1];
    const int*   cat_off = (const int*)d_in[2];
    const int*   edge    = (const int*)d_in[3];
    const float* cat_tab = (const float*)d_in[4];
    const float* fuse_w  = (const float*)d_in[5];
    const float* user    = (const float*)d_in[6];
    const float* w1_l    = (const float*)d_in[7];
    const float* b1      = (const float*)d_in[8];
    const float* w1_r    = (const float*)d_in[9];
    const float* w2_l    = (const float*)d_in[10];
    const float* b2      = (const float*)d_in[11];
    const float* w2_r    = (const float*)d_in[12];

    int E = in_sizes[3] / 2;
    const int* src = edge;
    const int* dst = edge + E;
    int tot_idx = in_sizes[1];

    float *x0p, *h1p, *s1p, *x1p, *h2p, *s2p, *catp, *degp;
    cudaGetSymbolAddress((void**)&x0p, g_x0);
    cudaGetSymbolAddress((void**)&h1p, g_h1);
    cudaGetSymbolAddress((void**)&s1p, g_s1);
    cudaGetSymbolAddress((void**)&x1p, g_x1);
    cudaGetSymbolAddress((void**)&h2p, g_h2);
    cudaGetSymbolAddress((void**)&s2p, g_s2);
    cudaGetSymbolAddress((void**)&catp, g_cat);
    cudaGetSymbolAddress((void**)&degp, g_deg);

    const int grid_item = (ITEM_NUM + 127) / 128;   // 391
    const int grid_all  = (NTOT + 127) / 128;       // 782

    // 1. zero scratch + copy user rows
    init_kernel<<<2048, 256>>>(user);
    // 2. cat embedding bag
    catbag_kernel<<<(ITEM_NUM * 8 + 255) / 256, 256>>>(cat_tab, cat_idx, cat_off, tot_idx);
    // 3. item_feat = [vt | cat] @ fuse_w.T  -> x0[USER:]
    gemm_kernel<128, 0, true><<<grid_item, 256>>>(
        vt, VT_DIM + CAT_DIM, catp, fuse_w, nullptr, nullptr, nullptr,
        x0p + (size_t)USER_NUM * HID, ITEM_NUM);
    // 4. degree
    deg_kernel<<<2048, 256>>>(dst, E);
    // 5. h1 = x0 @ w1_l.T
    gemm_kernel<128, 0, false><<<grid_all, 256>>>(
        x0p, HID, nullptr, w1_l, nullptr, nullptr, nullptr, h1p, NTOT);
    // 6. s1[dst] += h1[src]
    scatter_kernel<128><<<2048, 256>>>(h1p, src, dst, s1p, E);
    // 7. x1 = leaky(s1/deg + b1 + x0 @ w1_r.T)
    gemm_kernel<128, 1, false><<<grid_all, 256>>>(
        x0p, HID, nullptr, w1_r, b1, s1p, degp, x1p, NTOT);
    // 8. h2 = x1 @ w2_l.T
    gemm_kernel<64, 0, false><<<grid_all, 256>>>(
        x1p, HID, nullptr, w2_l, nullptr, nullptr, nullptr, h2p, NTOT);
    // 9. s2[dst] += h2[src]
    scatter_kernel<64><<<2048, 256>>>(h2p, src, dst, s2p, E);
    // 10. out = s2/deg + b2 + x1 @ w2_r.T
    gemm_kernel<64, 2, false><<<grid_all, 256>>>(
        x1p, HID, nullptr, w2_r, b2, s2p, degp, (float*)d_out, NTOT);
}

// round 6
// speedup vs baseline: 1.4365x; 1.2982x over previous
#include <cuda_runtime.h>
#include <cstdint>

#define USER_NUM 50000
#define ITEM_NUM 50000
#define NTOT     100000
#define VT_DIM   512
#define CAT_DIM  32
#define HID      128
#define OUTD     64
#define EMAX     2000000

// ---------------- static scratch (no allocs allowed) ----------------
__device__ float g_x0[(size_t)NTOT * HID];    // [user; item_feat]
__device__ float g_h1[(size_t)NTOT * HID];    // x0 @ w1_l.T
__device__ float g_s1[(size_t)NTOT * HID];    // aggregated sums (conv1)
__device__ float g_x1[(size_t)NTOT * HID];    // leaky(conv1)
__device__ float g_h2[(size_t)NTOT * OUTD];   // x1 @ w2_l.T
__device__ float g_s2[(size_t)NTOT * OUTD];   // aggregated sums (conv2)
__device__ float g_cat[(size_t)ITEM_NUM * CAT_DIM];
__device__ int   g_cnt[NTOT];                 // in-degree counts
__device__ int   g_fill[NTOT];                // bucket fill cursors
__device__ int   g_rowptr[NTOT];              // CSR row starts (exclusive scan)
__device__ int   g_csr_src[EMAX];             // src node per in-edge, bucketed by dst
__device__ int   g_bsum[256];                 // scan block sums
__device__ int   g_boff[256];                 // scanned block offsets

#define SCAN_B 512
#define SCAN_NB ((NTOT + SCAN_B - 1) / SCAN_B)   // 196

// ---------------- helpers ----------------
__device__ __forceinline__ void ffma2(unsigned long long& d,
                                      unsigned long long a,
                                      unsigned long long b) {
    asm("fma.rn.f32x2 %0, %1, %2, %0;" : "+l"(d) : "l"(a), "l"(b));
}
__device__ __forceinline__ unsigned long long pack_dup(float a) {
    unsigned long long r;
    asm("mov.b64 %0, {%1, %1};" : "=l"(r) : "f"(a));
    return r;
}
__device__ __forceinline__ void unpack2(unsigned long long v, float& lo, float& hi) {
    asm("mov.b64 {%0, %1}, %2;" : "=f"(lo), "=f"(hi) : "l"(v));
}

// ---------------- init: zero cnt/fill + copy user rows into x0 --------------
__global__ void init_kernel(const float* __restrict__ user) {
    size_t nu = (size_t)USER_NUM * HID / 4;
    size_t stride = (size_t)gridDim.x * blockDim.x;
    size_t gid = (size_t)blockIdx.x * blockDim.x + threadIdx.x;
    for (size_t i = gid; i < NTOT; i += stride) { g_cnt[i] = 0; g_fill[i] = 0; }
    for (size_t i = gid; i < nu; i += stride)
        ((float4*)g_x0)[i] = ((const float4*)user)[i];
}

// ---------------- embedding bag (mean of ~5 rows of 32) ----------------
__global__ void catbag_kernel(const float* __restrict__ table,
                              const int* __restrict__ idx,
                              const int* __restrict__ offs,
                              int tot_idx) {
    int gid = blockIdx.x * blockDim.x + threadIdx.x;
    if (gid >= ITEM_NUM * 8) return;
    int bag  = gid >> 3;
    int comp = (gid & 7) * 4;
    int beg = offs[bag];
    int end = (bag + 1 < ITEM_NUM) ? offs[bag + 1] : tot_idx;
    float4 s = make_float4(0.f, 0.f, 0.f, 0.f);
    for (int j = beg; j < end; j++) {
        int ix = __ldg(&idx[j]);
        float4 t = *(const float4*)(table + (size_t)ix * CAT_DIM + comp);
        s.x += t.x; s.y += t.y; s.z += t.z; s.w += t.w;
    }
    float inv = 1.0f / (float)max(end - beg, 1);
    s.x *= inv; s.y *= inv; s.z *= inv; s.w *= inv;
    *(float4*)(g_cat + (size_t)bag * CAT_DIM + comp) = s;
}

// ---------------- CSR build ----------------
__global__ void count_kernel(const int* __restrict__ dst, int E) {
    int stride = gridDim.x * blockDim.x;
    for (int e = blockIdx.x * blockDim.x + threadIdx.x; e < E; e += stride)
        atomicAdd(&g_cnt[__ldg(&dst[e])], 1);
}

__global__ void scan1_kernel() {
    __shared__ int sm[SCAN_B];
    int t = threadIdx.x;
    int i = blockIdx.x * SCAN_B + t;
    int v = (i < NTOT) ? g_cnt[i] : 0;
    sm[t] = v;
    __syncthreads();
#pragma unroll
    for (int off = 1; off < SCAN_B; off <<= 1) {
        int x = (t >= off) ? sm[t - off] : 0;
        __syncthreads();
        sm[t] += x;
        __syncthreads();
    }
    if (i < NTOT) g_rowptr[i] = sm[t] - v;      // exclusive within block
    if (t == SCAN_B - 1) g_bsum[blockIdx.x] = sm[t];
}

__global__ void scan2_kernel() {
    __shared__ int sm[256];
    int t = threadIdx.x;
    int v = (t < SCAN_NB) ? g_bsum[t] : 0;
    sm[t] = v;
    __syncthreads();
#pragma unroll
    for (int off = 1; off < 256; off <<= 1) {
        int x = (t >= off) ? sm[t - off] : 0;
        __syncthreads();
        sm[t] += x;
        __syncthreads();
    }
    if (t < SCAN_NB) g_boff[t] = sm[t] - v;     // exclusive
}

__global__ void scan3_kernel() {
    int i = blockIdx.x * SCAN_B + threadIdx.x;
    if (i < NTOT) g_rowptr[i] += g_boff[blockIdx.x];
}

__global__ void fill_kernel(const int* __restrict__ src,
                            const int* __restrict__ dst, int E) {
    int stride = gridDim.x * blockDim.x;
    for (int e = blockIdx.x * blockDim.x + threadIdx.x; e < E; e += stride) {
        int d = __ldg(&dst[e]);
        int pos = g_rowptr[d] + atomicAdd(&g_fill[d], 1);
        g_csr_src[pos] = __ldg(&src[e]);
    }
}

// ---------------- CSR gather-aggregate: s[n] = sum_{j in in(n)} h[j] --------
// NC=128: one warp per node. NC=64: half-warp per node.
template <int NC>
__global__ void agg_kernel(const float* __restrict__ h, float* __restrict__ s) {
    constexpr int LPE = NC / 4;                   // lanes per node (32 or 16)
    int gt = blockIdx.x * blockDim.x + threadIdx.x;
    int node = gt / LPE;
    int lane = threadIdx.x & (LPE - 1);
    if (node >= NTOT) return;
    int co = lane * 4;
    int beg = __ldg(&g_rowptr[node]);
    int end = beg + __ldg(&g_cnt[node]);
    float4 acc = make_float4(0.f, 0.f, 0.f, 0.f);
    int j = beg;
    for (; j + 1 < end; j += 2) {
        int s0 = __ldg(&g_csr_src[j]);
        int s1 = __ldg(&g_csr_src[j + 1]);
        float4 v0 = *(const float4*)(h + (size_t)s0 * NC + co);
        float4 v1 = *(const float4*)(h + (size_t)s1 * NC + co);
        acc.x += v0.x + v1.x; acc.y += v0.y + v1.y;
        acc.z += v0.z + v1.z; acc.w += v0.w + v1.w;
    }
    if (j < end) {
        int s0 = __ldg(&g_csr_src[j]);
        float4 v0 = *(const float4*)(h + (size_t)s0 * NC + co);
        acc.x += v0.x; acc.y += v0.y; acc.z += v0.z; acc.w += v0.w;
    }
    *(float4*)(s + (size_t)node * NC + co) = acc;
}

// ---- pipelined FFMA2 GEMM: C[M,NC] = A[M,K] @ W[NC,K]^T (+epilogue) --------
// BM=128, BK=16, 256 threads (exact R3 configuration)
// EPI: 0 = plain, 1 = leaky(C + b + s/deg), 2 = C + b + s/deg
template <int NC, int EPI, bool FUSED>
__global__ __launch_bounds__(256, 2)
void gemm_kernel(const float* __restrict__ A, int K,
                 const float* __restrict__ A2,
                 const float* __restrict__ W,
                 const float* __restrict__ bias,
                 const float* __restrict__ sagg,
                 const int* __restrict__ cntp,
                 float* __restrict__ C, int M) {
    constexpr int BM = 128, BK = 16;
    constexpr int WPT = NC / 64;
    constexpr int NG  = NC / 64;
    constexpr int CP2 = NC / 32;
    constexpr int WST = NC + 4;

    __shared__ float As[2][BM][BK + 4];
    __shared__ float Ws[2][BK][WST];

    int tid = threadIdx.x;
    int tx = tid & 15, ty = tid >> 4;
    int row0 = blockIdx.x * BM;
    int r0 = ty * 8;
    int c0 = tx * 4;

    unsigned long long acc2[8][CP2];
#pragma unroll
    for (int i = 0; i < 8; i++)
#pragma unroll
        for (int j = 0; j < CP2; j++) acc2[i][j] = 0ull;

    float4 ar[2], wr[WPT];
    int nch = K / BK;

    auto ldgA = [&](int ch) {
        int kk = ch * BK;
#pragma unroll
        for (int h = 0; h < 2; h++) {
            int f = tid + h * 256;
            int row = f >> 2;
            int kc = (f & 3) * 4;
            int grow = row0 + row;
            float4 v = make_float4(0.f, 0.f, 0.f, 0.f);
            if (grow < M) {
                if (!FUSED)
                    v = *(const float4*)(A + (size_t)grow * K + kk + kc);
                else if (kk < VT_DIM)
                    v = *(const float4*)(A + (size_t)grow * VT_DIM + kk + kc);
                else
                    v = *(const float4*)(A2 + (size_t)grow * CAT_DIM + (kk - VT_DIM) + kc);
            }
            ar[h] = v;
        }
    };
    auto ldgW = [&](int ch) {
        int kk = ch * BK;
#pragma unroll
        for (int h = 0; h < WPT; h++) {
            int f = tid + h * 256;
            int c = f >> 2;
            int kq = (f & 3) * 4;
            wr[h] = *(const float4*)(W + (size_t)c * K + kk + kq);
        }
    };
    auto sts = [&](int b) {
#pragma unroll
        for (int h = 0; h < 2; h++) {
            int f = tid + h * 256;
            *(float4*)&As[b][f >> 2][(f & 3) * 4] = ar[h];
        }
#pragma unroll
        for (int h = 0; h < WPT; h++) {
            int f = tid + h * 256;
            int c = f >> 2;
            int kq = (f & 3) * 4;
            Ws[b][kq + 0][c] = wr[h].x;
            Ws[b][kq + 1][c] = wr[h].y;
            Ws[b][kq + 2][c] = wr[h].z;
            Ws[b][kq + 3][c] = wr[h].w;
        }
    };
    auto compute = [&](int b) {
#pragma unroll
        for (int k2 = 0; k2 < BK; k2 += 2) {
            ulonglong2 w0[NG], w1[NG];
#pragma unroll
            for (int g = 0; g < NG; g++) {
                w0[g] = *(const ulonglong2*)&Ws[b][k2 + 0][c0 + g * 64];
                w1[g] = *(const ulonglong2*)&Ws[b][k2 + 1][c0 + g * 64];
            }
#pragma unroll
            for (int i = 0; i < 8; i++) {
                float2 t = *(const float2*)&As[b][r0 + i][k2];
                unsigned long long pa0 = pack_dup(t.x);
                unsigned long long pa1 = pack_dup(t.y);
#pragma unroll
                for (int g = 0; g < NG; g++) {
                    ffma2(acc2[i][2 * g + 0], pa0, w0[g].x);
                    ffma2(acc2[i][2 * g + 1], pa0, w0[g].y);
                    ffma2(acc2[i][2 * g + 0], pa1, w1[g].x);
                    ffma2(acc2[i][2 * g + 1], pa1, w1[g].y);
                }
            }
        }
    };

    ldgA(0); ldgW(0);
    sts(0);
    __syncthreads();

    for (int ch = 0; ch < nch; ch++) {
        int nb = ch & 1;
        if (ch + 1 < nch) { ldgA(ch + 1); ldgW(ch + 1); }
        compute(nb);
        if (ch + 1 < nch) sts(1 - nb);
        __syncthreads();
    }

#pragma unroll
    for (int i = 0; i < 8; i++) {
        int gr = row0 + r0 + i;
        if (gr >= M) continue;
        float dinv = 0.f;
        if (EPI != 0) dinv = 1.0f / fmaxf((float)cntp[gr], 1.0f);
#pragma unroll
        for (int g = 0; g < NG; g++) {
            int gc = c0 + g * 64;
            float4 v;
            unpack2(acc2[i][2 * g + 0], v.x, v.y);
            unpack2(acc2[i][2 * g + 1], v.z, v.w);
            if (EPI != 0) {
                float4 sv = *(const float4*)(sagg + (size_t)gr * NC + gc);
                v.x += bias[gc + 0] + sv.x * dinv;
                v.y += bias[gc + 1] + sv.y * dinv;
                v.z += bias[gc + 2] + sv.z * dinv;
                v.w += bias[gc + 3] + sv.w * dinv;
                if (EPI == 1) {
                    v.x = v.x > 0.f ? v.x : 0.01f * v.x;
                    v.y = v.y > 0.f ? v.y : 0.01f * v.y;
                    v.z = v.z > 0.f ? v.z : 0.01f * v.z;
                    v.w = v.w > 0.f ? v.w : 0.01f * v.w;
                }
            }
            *(float4*)(C + (size_t)gr * NC + gc) = v;
        }
    }
}

// ---------------- launch ----------------
extern "C" void kernel_launch(void* const* d_in, const int* in_sizes, int n_in,
                              void* d_out, int out_size) {
    const float* vt      = (const float*)d_in[0];
    const int*   cat_idx = (const int*)d_in[1];
    const int*   cat_off = (const int*)d_in[2];
    const int*   edge    = (const int*)d_in[3];
    const float* cat_tab = (const float*)d_in[4];
    const float* fuse_w  = (const float*)d_in[5];
    const float* user    = (const float*)d_in[6];
    const float* w1_l    = (const float*)d_in[7];
    const float* b1      = (const float*)d_in[8];
    const float* w1_r    = (const float*)d_in[9];
    const float* w2_l    = (const float*)d_in[10];
    const float* b2      = (const float*)d_in[11];
    const float* w2_r    = (const float*)d_in[12];

    int E = in_sizes[3] / 2;
    const int* src = edge;
    const int* dst = edge + E;
    int tot_idx = in_sizes[1];

    float *x0p, *h1p, *s1p, *x1p, *h2p, *s2p, *catp;
    int *cntp;
    cudaGetSymbolAddress((void**)&x0p, g_x0);
    cudaGetSymbolAddress((void**)&h1p, g_h1);
    cudaGetSymbolAddress((void**)&s1p, g_s1);
    cudaGetSymbolAddress((void**)&x1p, g_x1);
    cudaGetSymbolAddress((void**)&h2p, g_h2);
    cudaGetSymbolAddress((void**)&s2p, g_s2);
    cudaGetSymbolAddress((void**)&catp, g_cat);
    cudaGetSymbolAddress((void**)&cntp, g_cnt);

    const int grid_item = (ITEM_NUM + 127) / 128;   // 391
    const int grid_all  = (NTOT + 127) / 128;       // 782

    // 1. zero counters + copy user rows
    init_kernel<<<1024, 256>>>(user);
    // 2. cat embedding bag
    catbag_kernel<<<(ITEM_NUM * 8 + 255) / 256, 256>>>(cat_tab, cat_idx, cat_off, tot_idx);
    // 3. CSR: count
    count_kernel<<<2048, 256>>>(dst, E);
    // 4. CSR: exclusive scan (3 passes)
    scan1_kernel<<<SCAN_NB, SCAN_B>>>();
    scan2_kernel<<<1, 256>>>();
    scan3_kernel<<<SCAN_NB, SCAN_B>>>();
    // 5. CSR: bucket fill
    fill_kernel<<<2048, 256>>>(src, dst, E);
    // 6. item_feat = [vt | cat] @ fuse_w.T  -> x0[USER:]
    gemm_kernel<128, 0, true><<<grid_item, 256>>>(
        vt, VT_DIM + CAT_DIM, catp, fuse_w, nullptr, nullptr, nullptr,
        x0p + (size_t)USER_NUM * HID, ITEM_NUM);
    // 7. h1 = x0 @ w1_l.T
    gemm_kernel<128, 0, false><<<grid_all, 256>>>(
        x0p, HID, nullptr, w1_l, nullptr, nullptr, nullptr, h1p, NTOT);
    // 8. s1[n] = sum_{j->n} h1[j]   (CSR gather, no atomics)
    agg_kernel<128><<<(NTOT * 32 + 255) / 256, 256>>>(h1p, s1p);
    // 9. x1 = leaky(s1/deg + b1 + x0 @ w1_r.T)
    gemm_kernel<128, 1, false><<<grid_all, 256>>>(
        x0p, HID, nullptr, w1_r, b1, s1p, cntp, x1p, NTOT);
    // 10. h2 = x1 @ w2_l.T
    gemm_kernel<64, 0, false><<<grid_all, 256>>>(
        x1p, HID, nullptr, w2_l, nullptr, nullptr, nullptr, h2p, NTOT);
    // 11. s2[n] = sum_{j->n} h2[j]
    agg_kernel<64><<<(NTOT * 16 + 255) / 256, 256>>>(h2p, s2p);
    // 12. out = s2/deg + b2 + x1 @ w2_r.T
    gemm_kernel<64, 2, false><<<grid_all, 256>>>(
        x1p, HID, nullptr, w2_r, b2, s2p, cntp, (float*)d_out, NTOT);
}

// round 8
// speedup vs baseline: 1.5581x; 1.0847x over previous
#include <cuda_runtime.h>
#include <cstdint>

#define USER_NUM 50000
#define ITEM_NUM 50000
#define NTOT     100000
#define VT_DIM   512
#define CAT_DIM  32
#define HID      128
#define OUTD     64
#define EMAX     2000000

// ---------------- static scratch (no allocs allowed) ----------------
__device__ float g_x0[(size_t)NTOT * HID];
__device__ float g_h1[(size_t)NTOT * HID];
__device__ float g_s1[(size_t)NTOT * HID];
__device__ float g_r1[(size_t)NTOT * HID];
__device__ float g_x1[(size_t)NTOT * HID];
__device__ float g_h2[(size_t)NTOT * OUTD];
__device__ float g_s2[(size_t)NTOT * OUTD];
__device__ float g_r2[(size_t)NTOT * OUTD];
__device__ float g_cat[(size_t)ITEM_NUM * CAT_DIM];
__device__ int   g_cnt[NTOT];
__device__ int   g_fill[NTOT];
__device__ int   g_rowptr[NTOT];
__device__ int   g_csr_src[EMAX];
__device__ int   g_bsum[256];
__device__ int   g_boff[256];

#define SCAN_B 512
#define SCAN_NB ((NTOT + SCAN_B - 1) / SCAN_B)

// ---------------- helpers ----------------
__device__ __forceinline__ void ffma2(unsigned long long& d,
                                      unsigned long long a,
                                      unsigned long long b) {
    asm("fma.rn.f32x2 %0, %1, %2, %0;" : "+l"(d) : "l"(a), "l"(b));
}
__device__ __forceinline__ unsigned long long pack_dup(float a) {
    unsigned long long r;
    asm("mov.b64 %0, {%1, %1};" : "=l"(r) : "f"(a));
    return r;
}
__device__ __forceinline__ void unpack2(unsigned long long v, float& lo, float& hi) {
    asm("mov.b64 {%0, %1}, %2;" : "=f"(lo), "=f"(hi) : "l"(v));
}

// ---------------- init: zero cnt/fill + copy user rows into x0 --------------
__global__ void init_kernel(const float* __restrict__ user) {
    size_t nu = (size_t)USER_NUM * HID / 4;
    size_t stride = (size_t)gridDim.x * blockDim.x;
    size_t gid = (size_t)blockIdx.x * blockDim.x + threadIdx.x;
    for (size_t i = gid; i < NTOT; i += stride) { g_cnt[i] = 0; g_fill[i] = 0; }
    for (size_t i = gid; i < nu; i += stride)
        ((float4*)g_x0)[i] = ((const float4*)user)[i];
}

// ---------------- embedding bag ----------------
__global__ void catbag_kernel(const float* __restrict__ table,
                              const int* __restrict__ idx,
                              const int* __restrict__ offs,
                              int tot_idx) {
    int gid = blockIdx.x * blockDim.x + threadIdx.x;
    if (gid >= ITEM_NUM * 8) return;
    int bag  = gid >> 3;
    int comp = (gid & 7) * 4;
    int beg = offs[bag];
    int end = (bag + 1 < ITEM_NUM) ? offs[bag + 1] : tot_idx;
    float4 s = make_float4(0.f, 0.f, 0.f, 0.f);
    for (int j = beg; j < end; j++) {
        int ix = __ldg(&idx[j]);
        float4 t = *(const float4*)(table + (size_t)ix * CAT_DIM + comp);
        s.x += t.x; s.y += t.y; s.z += t.z; s.w += t.w;
    }
    float inv = 1.0f / (float)max(end - beg, 1);
    s.x *= inv; s.y *= inv; s.z *= inv; s.w *= inv;
    *(float4*)(g_cat + (size_t)bag * CAT_DIM + comp) = s;
}

// ---------------- CSR build ----------------
__global__ void count_kernel(const int* __restrict__ dst, int E) {
    int stride = gridDim.x * blockDim.x;
    for (int e = blockIdx.x * blockDim.x + threadIdx.x; e < E; e += stride)
        atomicAdd(&g_cnt[__ldg(&dst[e])], 1);
}

__global__ void scan1_kernel() {
    __shared__ int sm[SCAN_B];
    int t = threadIdx.x;
    int i = blockIdx.x * SCAN_B + t;
    int v = (i < NTOT) ? g_cnt[i] : 0;
    sm[t] = v;
    __syncthreads();
#pragma unroll
    for (int off = 1; off < SCAN_B; off <<= 1) {
        int x = (t >= off) ? sm[t - off] : 0;
        __syncthreads();
        sm[t] += x;
        __syncthreads();
    }
    if (i < NTOT) g_rowptr[i] = sm[t] - v;
    if (t == SCAN_B - 1) g_bsum[blockIdx.x] = sm[t];
}

__global__ void scan2_kernel() {
    __shared__ int sm[256];
    int t = threadIdx.x;
    int v = (t < SCAN_NB) ? g_bsum[t] : 0;
    sm[t] = v;
    __syncthreads();
#pragma unroll
    for (int off = 1; off < 256; off <<= 1) {
        int x = (t >= off) ? sm[t - off] : 0;
        __syncthreads();
        sm[t] += x;
        __syncthreads();
    }
    if (t < SCAN_NB) g_boff[t] = sm[t] - v;
}

__global__ void scan3_kernel() {
    int i = blockIdx.x * SCAN_B + threadIdx.x;
    if (i < NTOT) g_rowptr[i] += g_boff[blockIdx.x];
}

__global__ void fill_kernel(const int* __restrict__ src,
                            const int* __restrict__ dst, int E) {
    int stride = gridDim.x * blockDim.x;
    for (int e = blockIdx.x * blockDim.x + threadIdx.x; e < E; e += stride) {
        int d = __ldg(&dst[e]);
        int pos = g_rowptr[d] + atomicAdd(&g_fill[d], 1);
        g_csr_src[pos] = __ldg(&src[e]);
    }
}

// ---------------- CSR gather-aggregate ----------------
template <int NC>
__global__ void agg_kernel(const float* __restrict__ h, float* __restrict__ s) {
    constexpr int LPE = NC / 4;
    int gt = blockIdx.x * blockDim.x + threadIdx.x;
    int node = gt / LPE;
    int lane = threadIdx.x & (LPE - 1);
    if (node >= NTOT) return;
    int co = lane * 4;
    int beg = __ldg(&g_rowptr[node]);
    int end = beg + __ldg(&g_cnt[node]);
    float4 acc = make_float4(0.f, 0.f, 0.f, 0.f);
    int j = beg;
    for (; j + 1 < end; j += 2) {
        int s0 = __ldg(&g_csr_src[j]);
        int s1 = __ldg(&g_csr_src[j + 1]);
        float4 v0 = *(const float4*)(h + (size_t)s0 * NC + co);
        float4 v1 = *(const float4*)(h + (size_t)s1 * NC + co);
        acc.x += v0.x + v1.x; acc.y += v0.y + v1.y;
        acc.z += v0.z + v1.z; acc.w += v0.w + v1.w;
    }
    if (j < end) {
        int s0 = __ldg(&g_csr_src[j]);
        float4 v0 = *(const float4*)(h + (size_t)s0 * NC + co);
        acc.x += v0.x; acc.y += v0.y; acc.z += v0.z; acc.w += v0.w;
    }
    *(float4*)(s + (size_t)node * NC + co) = acc;
}

// ---------------- combine: out = [leaky](s/deg + b + r) ---------------------
template <int NC, bool LEAKY>
__global__ void combine_kernel(const float* __restrict__ s,
                               const float* __restrict__ r,
                               const float* __restrict__ bias,
                               float* __restrict__ out) {
    constexpr int LPN = NC / 4;
    size_t gid = (size_t)blockIdx.x * blockDim.x + threadIdx.x;
    if (gid >= (size_t)NTOT * LPN) return;
    int node = gid / LPN;
    int c = (gid % LPN) * 4;
    float dinv = 1.0f / fmaxf((float)__ldg(&g_cnt[node]), 1.0f);
    float4 sv = ((const float4*)s)[gid];
    float4 rv = ((const float4*)r)[gid];
    float4 bv = *(const float4*)(bias + c);
    float4 v;
    v.x = sv.x * dinv + bv.x + rv.x;
    v.y = sv.y * dinv + bv.y + rv.y;
    v.z = sv.z * dinv + bv.z + rv.z;
    v.w = sv.w * dinv + bv.w + rv.w;
    if (LEAKY) {
        v.x = v.x > 0.f ? v.x : 0.01f * v.x;
        v.y = v.y > 0.f ? v.y : 0.01f * v.y;
        v.z = v.z > 0.f ? v.z : 0.01f * v.z;
        v.w = v.w > 0.f ? v.w : 0.01f * v.w;
    }
    ((float4*)out)[gid] = v;
}

// ---- pipelined FFMA2 GEMM: C[M,NC] = A[M,K] @ W[NC,K]^T --------------------
template <int NC, bool FUSED>
__global__ __launch_bounds__(256, 2)
void gemm_kernel(const float* __restrict__ A, int K,
                 const float* __restrict__ A2,
                 const float* __restrict__ W,
                 float* __restrict__ C, int M) {
    constexpr int BM = 128, BK = 16;
    constexpr int WPT = NC / 64;
    constexpr int NG  = NC / 64;
    constexpr int CP2 = NC / 32;
    constexpr int WST = NC + 4;

    __shared__ float As[2][BM][BK + 4];
    __shared__ float Ws[2][BK][WST];

    int tid = threadIdx.x;
    int tx = tid & 15, ty = tid >> 4;
    int row0 = blockIdx.x * BM;
    int r0 = ty * 8;
    int c0 = tx * 4;

    unsigned long long acc2[8][CP2];
#pragma unroll
    for (int i = 0; i < 8; i++)
#pragma unroll
        for (int j = 0; j < CP2; j++) acc2[i][j] = 0ull;

    float4 ar[2], wr[WPT];
    int nch = K / BK;

    auto ldgA = [&](int ch) {
        int kk = ch * BK;
#pragma unroll
        for (int h = 0; h < 2; h++) {
            int f = tid + h * 256;
            int row = f >> 2;
            int kc = (f & 3) * 4;
            int grow = row0 + row;
            float4 v = make_float4(0.f, 0.f, 0.f, 0.f);
            if (grow < M) {
                if (!FUSED)
                    v = *(const float4*)(A + (size_t)grow * K + kk + kc);
                else if (kk < VT_DIM)
                    v = *(const float4*)(A + (size_t)grow * VT_DIM + kk + kc);
                else
                    v = *(const float4*)(A2 + (size_t)grow * CAT_DIM + (kk - VT_DIM) + kc);
            }
            ar[h] = v;
        }
    };
    auto ldgW = [&](int ch) {
        int kk = ch * BK;
#pragma unroll
        for (int h = 0; h < WPT; h++) {
            int f = tid + h * 256;
            int c = f >> 2;
            int kq = (f & 3) * 4;
            wr[h] = *(const float4*)(W + (size_t)c * K + kk + kq);
        }
    };
    auto sts = [&](int b) {
#pragma unroll
        for (int h = 0; h < 2; h++) {
            int f = tid + h * 256;
            *(float4*)&As[b][f >> 2][(f & 3) * 4] = ar[h];
        }
#pragma unroll
        for (int h = 0; h < WPT; h++) {
            int f = tid + h * 256;
            int c = f >> 2;
            int kq = (f & 3) * 4;
            Ws[b][kq + 0][c] = wr[h].x;
            Ws[b][kq + 1][c] = wr[h].y;
            Ws[b][kq + 2][c] = wr[h].z;
            Ws[b][kq + 3][c] = wr[h].w;
        }
    };
    auto compute = [&](int b) {
#pragma unroll
        for (int k2 = 0; k2 < BK; k2 += 2) {
            ulonglong2 w0[NG], w1[NG];
#pragma unroll
            for (int g = 0; g < NG; g++) {
                w0[g] = *(const ulonglong2*)&Ws[b][k2 + 0][c0 + g * 64];
                w1[g] = *(const ulonglong2*)&Ws[b][k2 + 1][c0 + g * 64];
            }
#pragma unroll
            for (int i = 0; i < 8; i++) {
                float2 t = *(const float2*)&As[b][r0 + i][k2];
                unsigned long long pa0 = pack_dup(t.x);
                unsigned long long pa1 = pack_dup(t.y);
#pragma unroll
                for (int g = 0; g < NG; g++) {
                    ffma2(acc2[i][2 * g + 0], pa0, w0[g].x);
                    ffma2(acc2[i][2 * g + 1], pa0, w0[g].y);
                    ffma2(acc2[i][2 * g + 0], pa1, w1[g].x);
                    ffma2(acc2[i][2 * g + 1], pa1, w1[g].y);
                }
            }
        }
    };

    ldgA(0); ldgW(0);
    sts(0);
    __syncthreads();

    for (int ch = 0; ch < nch; ch++) {
        int nb = ch & 1;
        if (ch + 1 < nch) { ldgA(ch + 1); ldgW(ch + 1); }
        compute(nb);
        if (ch + 1 < nch) sts(1 - nb);
        __syncthreads();
    }

#pragma unroll
    for (int i = 0; i < 8; i++) {
        int gr = row0 + r0 + i;
        if (gr >= M) continue;
#pragma unroll
        for (int g = 0; g < NG; g++) {
            int gc = c0 + g * 64;
            float4 v;
            unpack2(acc2[i][2 * g + 0], v.x, v.y);
            unpack2(acc2[i][2 * g + 1], v.z, v.w);
            *(float4*)(C + (size_t)gr * NC + gc) = v;
        }
    }
}

// tiny no-op kernel used as a fork anchor on the capturing stream
__global__ void fork_kernel() {}

// ---------------- launch ----------------
extern "C" void kernel_launch(void* const* d_in, const int* in_sizes, int n_in,
                              void* d_out, int out_size) {
    const float* vt      = (const float*)d_in[0];
    const int*   cat_idx = (const int*)d_in[1];
    const int*   cat_off = (const int*)d_in[2];
    const int*   edge    = (const int*)d_in[3];
    const float* cat_tab = (const float*)d_in[4];
    const float* fuse_w  = (const float*)d_in[5];
    const float* user    = (const float*)d_in[6];
    const float* w1_l    = (const float*)d_in[7];
    const float* b1      = (const float*)d_in[8];
    const float* w1_r    = (const float*)d_in[9];
    const float* w2_l    = (const float*)d_in[10];
    const float* b2      = (const float*)d_in[11];
    const float* w2_r    = (const float*)d_in[12];

    int E = in_sizes[3] / 2;
    const int* src = edge;
    const int* dst = edge + E;
    int tot_idx = in_sizes[1];

    float *x0p, *h1p, *s1p, *r1p, *x1p, *h2p, *s2p, *r2p, *catp;
    cudaGetSymbolAddress((void**)&x0p, g_x0);
    cudaGetSymbolAddress((void**)&h1p, g_h1);
    cudaGetSymbolAddress((void**)&s1p, g_s1);
    cudaGetSymbolAddress((void**)&r1p, g_r1);
    cudaGetSymbolAddress((void**)&x1p, g_x1);
    cudaGetSymbolAddress((void**)&h2p, g_h2);
    cudaGetSymbolAddress((void**)&s2p, g_s2);
    cudaGetSymbolAddress((void**)&r2p, g_r2);
    cudaGetSymbolAddress((void**)&catp, g_cat);

    // lazily-created side stream + events (created on first, non-captured call)
    static cudaStream_t sB = nullptr;
    static cudaEvent_t eFork, eCsr, eX0, eR1, eX1, eR2;
    if (!sB) {
        cudaStreamCreateWithFlags(&sB, cudaStreamNonBlocking);
        cudaEventCreateWithFlags(&eFork, cudaEventDisableTiming);
        cudaEventCreateWithFlags(&eCsr,  cudaEventDisableTiming);
        cudaEventCreateWithFlags(&eX0,   cudaEventDisableTiming);
        cudaEventCreateWithFlags(&eR1,   cudaEventDisableTiming);
        cudaEventCreateWithFlags(&eX1,   cudaEventDisableTiming);
        cudaEventCreateWithFlags(&eR2,   cudaEventDisableTiming);
    }
    cudaStream_t sA = 0;   // origin (captured) stream

    const int grid_item = (ITEM_NUM + 127) / 128;   // 391
    const int grid_all  = (NTOT + 127) / 128;       // 782
    const int grid_c1   = (NTOT * (HID / 4) + 255) / 256;
    const int grid_c2   = (NTOT * (OUTD / 4) + 255) / 256;

    // ---- fork: sB joins the capture via an event recorded on sA ----
    fork_kernel<<<1, 32, 0, sA>>>();
    cudaEventRecord(eFork, sA);
    cudaStreamWaitEvent(sB, eFork, 0);

    // ---- side stream: init (x0 user part, counters) + CSR build ----
    init_kernel<<<1024, 256, 0, sB>>>(user);
    count_kernel<<<2048, 256, 0, sB>>>(dst, E);
    scan1_kernel<<<SCAN_NB, SCAN_B, 0, sB>>>();
    scan2_kernel<<<1, 256, 0, sB>>>();
    scan3_kernel<<<SCAN_NB, SCAN_B, 0, sB>>>();
    fill_kernel<<<2048, 256, 0, sB>>>(src, dst, E);
    cudaEventRecord(eCsr, sB);

    // ---- main stream: features ----
    catbag_kernel<<<(ITEM_NUM * 8 + 255) / 256, 256, 0, sA>>>(cat_tab, cat_idx, cat_off, tot_idx);
    gemm_kernel<128, true><<<grid_item, 256, 0, sA>>>(
        vt, VT_DIM + CAT_DIM, catp, fuse_w, x0p + (size_t)USER_NUM * HID, ITEM_NUM);
    cudaStreamWaitEvent(sA, eCsr, 0);      // init (user rows) + CSR done
    cudaEventRecord(eX0, sA);              // x0 fully ready

    // conv1: h1 + agg1 on main; r1 on side (runs parallel with h1/agg1)
    cudaStreamWaitEvent(sB, eX0, 0);
    gemm_kernel<128, false><<<grid_all, 256, 0, sB>>>(
        x0p, HID, nullptr, w1_r, r1p, NTOT);
    cudaEventRecord(eR1, sB);

    gemm_kernel<128, false><<<grid_all, 256, 0, sA>>>(
        x0p, HID, nullptr, w1_l, h1p, NTOT);
    agg_kernel<128><<<(NTOT * 32 + 255) / 256, 256, 0, sA>>>(h1p, s1p);
    cudaStreamWaitEvent(sA, eR1, 0);
    combine_kernel<128, true><<<grid_c1, 256, 0, sA>>>(s1p, r1p, b1, x1p);
    cudaEventRecord(eX1, sA);

    // conv2: h2 + agg2 on main; r2 on side
    cudaStreamWaitEvent(sB, eX1, 0);
    gemm_kernel<64, false><<<grid_all, 256, 0, sB>>>(
        x1p, HID, nullptr, w2_r, r2p, NTOT);
    cudaEventRecord(eR2, sB);

    gemm_kernel<64, false><<<grid_all, 256, 0, sA>>>(
        x1p, HID, nullptr, w2_l, h2p, NTOT);
    agg_kernel<64><<<(NTOT * 16 + 255) / 256, 256, 0, sA>>>(h2p, s2p);
    cudaStreamWaitEvent(sA, eR2, 0);   // join: sB fully merged back into sA
    combine_kernel<64, false><<<grid_c2, 256, 0, sA>>>(s2p, r2p, b2, (float*)d_out);
}